// round 8
// baseline (speedup 1.0000x reference)
#include <cuda_runtime.h>
#include <cstdint>

#define TSTEPS 512
#define H 20
#define NB 4            // batches per 4-lane group
#define NTHREADS 64     // 2 warps; warp = 8 groups x 4 lanes = 32 batches
#define NBLOCKS 128     // 128 * 64 = 8192 batches exactly
#define SUBSTRIDE 2008  // floats per sub weight copy (pad -> distinct 16B phases)

typedef unsigned long long u64;

__device__ __forceinline__ void ffma2(u64& acc, u64 a, u64 b) {
    asm("fma.rn.f32x2 %0, %1, %2, %0;" : "+l"(acc) : "l"(a), "l"(b));
}
__device__ __forceinline__ u64 pack2(float lo, float hi) {
    u64 r; asm("mov.b64 %0, {%1, %2};" : "=l"(r) : "f"(lo), "f"(hi)); return r;
}
__device__ __forceinline__ float2 unpack2(u64 v) {
    float2 r; asm("mov.b64 {%0, %1}, %2;" : "=f"(r.x), "=f"(r.y) : "l"(v)); return r;
}
// tanh via ex2.approx + rcp.approx, abs err ~2e-7. Clamp keeps result finite
// for any finite input (needed: pipeline warm-up/drain computes on dummies).
__device__ __forceinline__ float tanh_fast(float x) {
    float ax = fminf(fabsf(x), 15.0f);
    float e;
    asm("ex2.approx.f32 %0, %1;" : "=f"(e) : "f"(ax * 2.8853900817779268f));
    float rr;
    asm("rcp.approx.f32 %0, %1;" : "=f"(rr) : "f"(e + 1.0f));
    return copysignf((e - 1.0f) * rr, x);
}

// 4-lane butterfly all-gather: own 5 h values -> all 20, k-pair packed,
// in per-lane block order [sub, sub^1, sub^2, sub^3] (weights pre-permuted).
__device__ __forceinline__ void gather20(const float v[5], u64 hp[10]) {
    float a[10];
#pragma unroll
    for (int i = 0; i < 5; i++) {
        a[i]     = v[i];
        a[5 + i] = __shfl_xor_sync(0xffffffffu, v[i], 1);
    }
#pragma unroll
    for (int q = 0; q < 5; q++) hp[q] = pack2(a[2 * q], a[2 * q + 1]);
    float b[10];
#pragma unroll
    for (int i = 0; i < 10; i++) b[i] = __shfl_xor_sync(0xffffffffu, a[i], 2);
#pragma unroll
    for (int q = 0; q < 5; q++) hp[5 + q] = pack2(b[2 * q], b[2 * q + 1]);
}

__global__ __launch_bounds__(NTHREADS)
void rnn3_kernel(
    const float* __restrict__ x,
    const float* __restrict__ w_ih0, const float* __restrict__ w_hh0,
    const float* __restrict__ b_ih0, const float* __restrict__ b_hh0,
    const float* __restrict__ w_ih1, const float* __restrict__ w_hh1,
    const float* __restrict__ b_ih1, const float* __restrict__ b_hh1,
    const float* __restrict__ w_ih2, const float* __restrict__ w_hh2,
    const float* __restrict__ b_ih2, const float* __restrict__ b_hh2,
    const float* __restrict__ fc_w, const float* __restrict__ fc_b,
    float* __restrict__ out)
{
    // per-sub permuted weight copies: wp[sub][m][j][k], column k maps to
    // original column 5*(sub ^ (k/5)) + k%5.
    // m: 0=w_hh0 1=w_ih1 2=w_hh1 3=w_ih2 4=w_hh2
    __shared__ __align__(16) float wp[4 * SUBSTRIDE];

    const int tid = threadIdx.x;
    for (int idx = tid; idx < 4 * 2000; idx += NTHREADS) {
        int sb  = idx / 2000;
        int rem = idx % 2000;
        int m   = rem / 400;
        int r   = rem % 400;
        int j   = r / H;
        int k   = r % H;
        int oc  = 5 * (sb ^ (k / 5)) + (k % 5);
        const float* src = (m == 0) ? w_hh0 : (m == 1) ? w_ih1 :
                           (m == 2) ? w_hh1 : (m == 3) ? w_ih2 : w_hh2;
        wp[sb * SUBSTRIDE + (m * H + j) * H + k] = src[j * H + oc];
    }
    __syncthreads();

    const int lane  = tid & 31;
    const int warp  = tid >> 5;
    const int gi    = lane >> 2;
    const int sub   = lane & 3;
    const int j0    = sub * 5;
    const int bbase = blockIdx.x * 64 + warp * 32 + gi;   // batch i = bbase + 8*i

    const float* wsub = wp + sub * SUBSTRIDE + j0 * H;    // row jj of m: +m*400+jj*20

    float bias0[5], bias1[5], bias2[5], wih0r[5];
#pragma unroll
    for (int jj = 0; jj < 5; jj++) {
        int j = j0 + jj;
        bias0[jj] = b_ih0[j] + b_hh0[j];
        bias1[jj] = b_ih1[j] + b_hh1[j];
        bias2[jj] = b_ih2[j] + b_hh2[j];
        wih0r[jj] = w_ih0[j];
    }

    // own-form persistent hidden state
    float h0own[NB][5], h1own[NB][5], h2own[NB][5];
#pragma unroll
    for (int i = 0; i < NB; i++)
#pragma unroll
        for (int jj = 0; jj < 5; jj++) {
            h0own[i][jj] = 0.f; h1own[i][jj] = 0.f; h2own[i][jj] = 0.f;
        }

    float4 xq[NB];
#pragma unroll
    for (int i = 0; i < NB; i++) xq[i] = make_float4(0.f, 0.f, 0.f, 0.f);

    // Skewed pipeline: iteration s computes L0(s), L1(s-1), L2(s-2).
#pragma unroll 1
    for (int s = 0; s < TSTEPS + 2; s++) {
        if (((s & 3) == 0) && (s < TSTEPS)) {
#pragma unroll
            for (int i = 0; i < NB; i++)
                xq[i] = __ldg((const float4*)(x + (size_t)(bbase + 8 * i) * TSTEPS + s));
        }
        const int ph = s & 3;
        float xv[NB];
#pragma unroll
        for (int i = 0; i < NB; i++)
            xv[i] = (ph == 0) ? xq[i].x : (ph == 1) ? xq[i].y :
                    (ph == 2) ? xq[i].z : xq[i].w;

        u64 g[NB][10];
        u64 acc1[NB][5];

        // ===== phase A: gather h0(s-1); L0(s); L1 input-half (s-1) =====
#pragma unroll
        for (int i = 0; i < NB; i++) gather20(h0own[i], g[i]);
        {
            u64 acc0[NB][5];
#pragma unroll
            for (int i = 0; i < NB; i++)
#pragma unroll
                for (int jj = 0; jj < 5; jj++)
                    acc0[i][jj] = pack2(fmaf(xv[i], wih0r[jj], bias0[jj]), 0.f);
#pragma unroll
            for (int q = 0; q < 5; q++)
#pragma unroll
                for (int jj = 0; jj < 5; jj++) {
                    ulonglong2 w2 = ((const ulonglong2*)(wsub + jj * H))[q];       // m0
#pragma unroll
                    for (int i = 0; i < NB; i++) {
                        ffma2(acc0[i][jj], g[i][2*q],   w2.x);
                        ffma2(acc0[i][jj], g[i][2*q+1], w2.y);
                    }
                }
#pragma unroll
            for (int i = 0; i < NB; i++)
#pragma unroll
                for (int jj = 0; jj < 5; jj++) {
                    float2 p = unpack2(acc0[i][jj]);
                    h0own[i][jj] = tanh_fast(p.x + p.y);     // h0(s)
                }
        }
        // L1A(s-1): acc1 = bias1 + Wih1 @ h0(s-1)  (same gathered g)
#pragma unroll
        for (int i = 0; i < NB; i++)
#pragma unroll
            for (int jj = 0; jj < 5; jj++) acc1[i][jj] = pack2(bias1[jj], 0.f);
#pragma unroll
        for (int q = 0; q < 5; q++)
#pragma unroll
            for (int jj = 0; jj < 5; jj++) {
                ulonglong2 w2 = ((const ulonglong2*)(wsub + 400 + jj * H))[q];     // m1
#pragma unroll
                for (int i = 0; i < NB; i++) {
                    ffma2(acc1[i][jj], g[i][2*q],   w2.x);
                    ffma2(acc1[i][jj], g[i][2*q+1], w2.y);
                }
            }

        // ===== phase B: gather h1(s-2); L1 recurrent-half; L2 input-half =====
#pragma unroll
        for (int i = 0; i < NB; i++) gather20(h1own[i], g[i]);
#pragma unroll
        for (int q = 0; q < 5; q++)
#pragma unroll
            for (int jj = 0; jj < 5; jj++) {
                ulonglong2 w2 = ((const ulonglong2*)(wsub + 800 + jj * H))[q];     // m2
#pragma unroll
                for (int i = 0; i < NB; i++) {
                    ffma2(acc1[i][jj], g[i][2*q],   w2.x);
                    ffma2(acc1[i][jj], g[i][2*q+1], w2.y);
                }
            }
        if (s >= 1) {   // h1(s-1); keep h1(-1)=0 intact at s=0
#pragma unroll
            for (int i = 0; i < NB; i++)
#pragma unroll
                for (int jj = 0; jj < 5; jj++) {
                    float2 p = unpack2(acc1[i][jj]);
                    h1own[i][jj] = tanh_fast(p.x + p.y);
                }
        }
        u64 acc2[NB][5];
#pragma unroll
        for (int i = 0; i < NB; i++)
#pragma unroll
            for (int jj = 0; jj < 5; jj++) acc2[i][jj] = pack2(bias2[jj], 0.f);
#pragma unroll
        for (int q = 0; q < 5; q++)
#pragma unroll
            for (int jj = 0; jj < 5; jj++) {
                ulonglong2 w2 = ((const ulonglong2*)(wsub + 1200 + jj * H))[q];    // m3
#pragma unroll
                for (int i = 0; i < NB; i++) {
                    ffma2(acc2[i][jj], g[i][2*q],   w2.x);
                    ffma2(acc2[i][jj], g[i][2*q+1], w2.y);
                }
            }

        // ===== phase C: gather h2(s-3); L2 recurrent-half -> h2(s-2) =====
#pragma unroll
        for (int i = 0; i < NB; i++) gather20(h2own[i], g[i]);
#pragma unroll
        for (int q = 0; q < 5; q++)
#pragma unroll
            for (int jj = 0; jj < 5; jj++) {
                ulonglong2 w2 = ((const ulonglong2*)(wsub + 1600 + jj * H))[q];    // m4
#pragma unroll
                for (int i = 0; i < NB; i++) {
                    ffma2(acc2[i][jj], g[i][2*q],   w2.x);
                    ffma2(acc2[i][jj], g[i][2*q+1], w2.y);
                }
            }
        if (s >= 2) {   // h2(s-2); keep h2(-1)=0 intact for s<2
#pragma unroll
            for (int i = 0; i < NB; i++)
#pragma unroll
                for (int jj = 0; jj < 5; jj++) {
                    float2 p = unpack2(acc2[i][jj]);
                    h2own[i][jj] = tanh_fast(p.x + p.y);
                }
        }
    }
    // after s = TSTEPS+1: h2own = h2(TSTEPS-1)

    // ===== FC epilogue: out[b] = h2 . fc_w + fc_b =====
    const float fb = __ldg(&fc_b[0]);
#pragma unroll
    for (int i = 0; i < NB; i++) {
        float s = 0.f;
#pragma unroll
        for (int jj = 0; jj < 5; jj++)
            s += h2own[i][jj] * __ldg(&fc_w[j0 + jj]);
        s += __shfl_xor_sync(0xffffffffu, s, 1);
        s += __shfl_xor_sync(0xffffffffu, s, 2);
        if (sub == 0) out[bbase + 8 * i] = s + fb;
    }
}

extern "C" void kernel_launch(void* const* d_in, const int* in_sizes, int n_in,
                              void* d_out, int out_size) {
    (void)in_sizes; (void)n_in; (void)out_size;
    rnn3_kernel<<<NBLOCKS, NTHREADS>>>(
        (const float*)d_in[0],
        (const float*)d_in[1],  (const float*)d_in[2],
        (const float*)d_in[3],  (const float*)d_in[4],
        (const float*)d_in[5],  (const float*)d_in[6],
        (const float*)d_in[7],  (const float*)d_in[8],
        (const float*)d_in[9],  (const float*)d_in[10],
        (const float*)d_in[11], (const float*)d_in[12],
        (const float*)d_in[13], (const float*)d_in[14],
        (float*)d_out);
}

// round 9
// speedup vs baseline: 2.5764x; 2.5764x over previous
#include <cuda_runtime.h>
#include <cstdint>

#define TSTEPS 512
#define H 20
#define NB 2            // batches per 4-lane group
#define NTHREADS 64     // 2 warps; warp = 8 groups x 4 lanes
#define NBLOCKS 256     // 256 * 2 warps * 8 groups * NB = 8192 batches
#define SUBSTRIDE 2008  // floats per sub weight copy (pad -> distinct 16B phases)

typedef unsigned long long u64;

__device__ __forceinline__ void ffma2(u64& acc, u64 a, u64 b) {
    asm("fma.rn.f32x2 %0, %1, %2, %0;" : "+l"(acc) : "l"(a), "l"(b));
}
__device__ __forceinline__ u64 pack2(float lo, float hi) {
    u64 r; asm("mov.b64 %0, {%1, %2};" : "=l"(r) : "f"(lo), "f"(hi)); return r;
}
__device__ __forceinline__ float2 unpack2(u64 v) {
    float2 r; asm("mov.b64 {%0, %1}, %2;" : "=f"(r.x), "=f"(r.y) : "l"(v)); return r;
}
// tanh via ex2.approx + rcp.approx, abs err ~2e-7; clamp keeps drain-phase
// dummy values finite.
__device__ __forceinline__ float tanh_fast(float x) {
    float ax = fminf(fabsf(x), 15.0f);
    float e;
    asm("ex2.approx.f32 %0, %1;" : "=f"(e) : "f"(ax * 2.8853900817779268f));
    float rr;
    asm("rcp.approx.f32 %0, %1;" : "=f"(rr) : "f"(e + 1.0f));
    return copysignf((e - 1.0f) * rr, x);
}

// 4-lane butterfly all-gather: own 5 h values -> all 20, k-pair packed,
// per-lane block order [sub, sub^1, sub^2, sub^3] (weights pre-permuted).
__device__ __forceinline__ void gather20(const float v[5], u64 hp[10]) {
    float a[10];
#pragma unroll
    for (int i = 0; i < 5; i++) {
        a[i]     = v[i];
        a[5 + i] = __shfl_xor_sync(0xffffffffu, v[i], 1);
    }
#pragma unroll
    for (int q = 0; q < 5; q++) hp[q] = pack2(a[2 * q], a[2 * q + 1]);
    float b[10];
#pragma unroll
    for (int i = 0; i < 10; i++) b[i] = __shfl_xor_sync(0xffffffffu, a[i], 2);
#pragma unroll
    for (int q = 0; q < 5; q++) hp[5 + q] = pack2(b[2 * q], b[2 * q + 1]);
}

__global__ __launch_bounds__(NTHREADS)
void rnn3_kernel(
    const float* __restrict__ x,
    const float* __restrict__ w_ih0, const float* __restrict__ w_hh0,
    const float* __restrict__ b_ih0, const float* __restrict__ b_hh0,
    const float* __restrict__ w_ih1, const float* __restrict__ w_hh1,
    const float* __restrict__ b_ih1, const float* __restrict__ b_hh1,
    const float* __restrict__ w_ih2, const float* __restrict__ w_hh2,
    const float* __restrict__ b_ih2, const float* __restrict__ b_hh2,
    const float* __restrict__ fc_w, const float* __restrict__ fc_b,
    float* __restrict__ out)
{
    // per-sub permuted weight copies: wp[sub][m][j][k], column k maps to
    // original column 5*(sub ^ (k/5)) + k%5.
    // m: 0=w_hh0 1=w_ih1 2=w_hh1 3=w_ih2 4=w_hh2
    __shared__ __align__(16) float wp[4 * SUBSTRIDE];

    const int tid = threadIdx.x;
    for (int idx = tid; idx < 4 * 2000; idx += NTHREADS) {
        int sb  = idx / 2000;
        int rem = idx % 2000;
        int m   = rem / 400;
        int r   = rem % 400;
        int j   = r / H;
        int k   = r % H;
        int oc  = 5 * (sb ^ (k / 5)) + (k % 5);
        const float* src = (m == 0) ? w_hh0 : (m == 1) ? w_ih1 :
                           (m == 2) ? w_hh1 : (m == 3) ? w_ih2 : w_hh2;
        wp[sb * SUBSTRIDE + (m * H + j) * H + k] = src[j * H + oc];
    }
    __syncthreads();

    const int lane  = tid & 31;
    const int warp  = tid >> 5;
    const int gi    = lane >> 2;
    const int sub   = lane & 3;
    const int j0    = sub * 5;
    const int bbase = blockIdx.x * 32 + warp * 16 + gi;   // batch i = bbase + 8*i

    const float* wsub = wp + sub * SUBSTRIDE + j0 * H;

    float bias0[5], bias1[5], bias2[5], wih0r[5];
#pragma unroll
    for (int jj = 0; jj < 5; jj++) {
        int j = j0 + jj;
        bias0[jj] = b_ih0[j] + b_hh0[j];
        bias1[jj] = b_ih1[j] + b_hh1[j];
        bias2[jj] = b_ih2[j] + b_hh2[j];
        wih0r[jj] = w_ih0[j];
    }

    // own-form persistent hidden state (registers only)
    float h0own[NB][5], h1own[NB][5], h2own[NB][5];
#pragma unroll
    for (int i = 0; i < NB; i++)
#pragma unroll
        for (int jj = 0; jj < 5; jj++) {
            h0own[i][jj] = 0.f; h1own[i][jj] = 0.f; h2own[i][jj] = 0.f;
        }

    float4 xq[NB];
#pragma unroll
    for (int i = 0; i < NB; i++) xq[i] = make_float4(0.f, 0.f, 0.f, 0.f);

    // Skewed pipeline: iteration s computes L0(s), L1(s-1), L2(s-2).
    // The three layer chains are mutually independent within an iteration,
    // so their latency (shfl 26 / FFMA 4 / MUFU 16) overlaps.
#pragma unroll 1
    for (int s = 0; s < TSTEPS + 2; s++) {
        if (((s & 3) == 0) && (s < TSTEPS)) {
#pragma unroll
            for (int i = 0; i < NB; i++)
                xq[i] = __ldg((const float4*)(x + (size_t)(bbase + 8 * i) * TSTEPS + s));
        }
        const int ph = s & 3;
        float xv[NB];
#pragma unroll
        for (int i = 0; i < NB; i++)
            xv[i] = (ph == 0) ? xq[i].x : (ph == 1) ? xq[i].y :
                    (ph == 2) ? xq[i].z : xq[i].w;

        u64 g[NB][10];
        u64 acc1[NB][5];

        // ===== phase A: gather h0(s-1); L0(s); L1 input-half (s-1) =====
#pragma unroll
        for (int i = 0; i < NB; i++) gather20(h0own[i], g[i]);
        {
            u64 acc0[NB][5];
#pragma unroll
            for (int i = 0; i < NB; i++)
#pragma unroll
                for (int jj = 0; jj < 5; jj++)
                    acc0[i][jj] = pack2(fmaf(xv[i], wih0r[jj], bias0[jj]), 0.f);
#pragma unroll
            for (int q = 0; q < 5; q++)
#pragma unroll
                for (int jj = 0; jj < 5; jj++) {
                    ulonglong2 w2 = ((const ulonglong2*)(wsub + jj * H))[q];       // m0
#pragma unroll
                    for (int i = 0; i < NB; i++) {
                        ffma2(acc0[i][jj], g[i][2*q],   w2.x);
                        ffma2(acc0[i][jj], g[i][2*q+1], w2.y);
                    }
                }
#pragma unroll
            for (int i = 0; i < NB; i++)
#pragma unroll
                for (int jj = 0; jj < 5; jj++) {
                    float2 p = unpack2(acc0[i][jj]);
                    h0own[i][jj] = tanh_fast(p.x + p.y);     // h0(s)
                }
        }
        // L1 input-half: acc1 = bias1 + Wih1 @ h0(s-1)  (reuses gathered g)
#pragma unroll
        for (int i = 0; i < NB; i++)
#pragma unroll
            for (int jj = 0; jj < 5; jj++) acc1[i][jj] = pack2(bias1[jj], 0.f);
#pragma unroll
        for (int q = 0; q < 5; q++)
#pragma unroll
            for (int jj = 0; jj < 5; jj++) {
                ulonglong2 w2 = ((const ulonglong2*)(wsub + 400 + jj * H))[q];     // m1
#pragma unroll
                for (int i = 0; i < NB; i++) {
                    ffma2(acc1[i][jj], g[i][2*q],   w2.x);
                    ffma2(acc1[i][jj], g[i][2*q+1], w2.y);
                }
            }

        // ===== phase B: gather h1(s-2); L1 recurrent-half; L2 input-half =====
#pragma unroll
        for (int i = 0; i < NB; i++) gather20(h1own[i], g[i]);
#pragma unroll
        for (int q = 0; q < 5; q++)
#pragma unroll
            for (int jj = 0; jj < 5; jj++) {
                ulonglong2 w2 = ((const ulonglong2*)(wsub + 800 + jj * H))[q];     // m2
#pragma unroll
                for (int i = 0; i < NB; i++) {
                    ffma2(acc1[i][jj], g[i][2*q],   w2.x);
                    ffma2(acc1[i][jj], g[i][2*q+1], w2.y);
                }
            }
        if (s >= 1) {   // h1(s-1); keep h1(-1)=0 intact at s=0
#pragma unroll
            for (int i = 0; i < NB; i++)
#pragma unroll
                for (int jj = 0; jj < 5; jj++) {
                    float2 p = unpack2(acc1[i][jj]);
                    h1own[i][jj] = tanh_fast(p.x + p.y);
                }
        }
        u64 acc2[NB][5];
#pragma unroll
        for (int i = 0; i < NB; i++)
#pragma unroll
            for (int jj = 0; jj < 5; jj++) acc2[i][jj] = pack2(bias2[jj], 0.f);
#pragma unroll
        for (int q = 0; q < 5; q++)
#pragma unroll
            for (int jj = 0; jj < 5; jj++) {
                ulonglong2 w2 = ((const ulonglong2*)(wsub + 1200 + jj * H))[q];    // m3
#pragma unroll
                for (int i = 0; i < NB; i++) {
                    ffma2(acc2[i][jj], g[i][2*q],   w2.x);
                    ffma2(acc2[i][jj], g[i][2*q+1], w2.y);
                }
            }

        // ===== phase C: gather h2(s-3); L2 recurrent-half -> h2(s-2) =====
#pragma unroll
        for (int i = 0; i < NB; i++) gather20(h2own[i], g[i]);
#pragma unroll
        for (int q = 0; q < 5; q++)
#pragma unroll
            for (int jj = 0; jj < 5; jj++) {
                ulonglong2 w2 = ((const ulonglong2*)(wsub + 1600 + jj * H))[q];    // m4
#pragma unroll
                for (int i = 0; i < NB; i++) {
                    ffma2(acc2[i][jj], g[i][2*q],   w2.x);
                    ffma2(acc2[i][jj], g[i][2*q+1], w2.y);
                }
            }
        if (s >= 2) {   // h2(s-2); keep h2(-1)=0 intact for s<2
#pragma unroll
            for (int i = 0; i < NB; i++)
#pragma unroll
                for (int jj = 0; jj < 5; jj++) {
                    float2 p = unpack2(acc2[i][jj]);
                    h2own[i][jj] = tanh_fast(p.x + p.y);
                }
        }
    }
    // after s = TSTEPS+1: h2own = h2(TSTEPS-1)

    // ===== FC epilogue: out[b] = h2 . fc_w + fc_b =====
    const float fb = __ldg(&fc_b[0]);
#pragma unroll
    for (int i = 0; i < NB; i++) {
        float s = 0.f;
#pragma unroll
        for (int jj = 0; jj < 5; jj++)
            s += h2own[i][jj] * __ldg(&fc_w[j0 + jj]);
        s += __shfl_xor_sync(0xffffffffu, s, 1);
        s += __shfl_xor_sync(0xffffffffu, s, 2);
        if (sub == 0) out[bbase + 8 * i] = s + fb;
    }
}

extern "C" void kernel_launch(void* const* d_in, const int* in_sizes, int n_in,
                              void* d_out, int out_size) {
    (void)in_sizes; (void)n_in; (void)out_size;
    rnn3_kernel<<<NBLOCKS, NTHREADS>>>(
        (const float*)d_in[0],
        (const float*)d_in[1],  (const float*)d_in[2],
        (const float*)d_in[3],  (const float*)d_in[4],
        (const float*)d_in[5],  (const float*)d_in[6],
        (const float*)d_in[7],  (const float*)d_in[8],
        (const float*)d_in[9],  (const float*)d_in[10],
        (const float*)d_in[11], (const float*)d_in[12],
        (const float*)d_in[13], (const float*)d_in[14],
        (float*)d_out);
}